// round 2
// baseline (speedup 1.0000x reference)
#include <cuda_runtime.h>
#include <cuda_bf16.h>
#include <cstdint>
#include <cstddef>

typedef unsigned long long ull;

__device__ __forceinline__ void ffma2(ull& d, ull a, ull b){
    asm("fma.rn.f32x2 %0, %1, %2, %0;" : "+l"(d) : "l"(a), "l"(b));
}
__device__ __forceinline__ ull pk2(float x, float y){
    ull r; asm("mov.b64 %0, {%1, %2};" : "=l"(r) : "f"(x), "f"(y)); return r;
}
__device__ __forceinline__ float2 upk(ull a){
    float2 r; asm("mov.b64 {%0, %1}, %2;" : "=f"(r.x), "=f"(r.y) : "l"(a)); return r;
}

// ---------------- fixed shapes ----------------
#define BB 4
#define HF 128
#define WF 128
#define CF 256
#define HC 64
#define WC 64
#define CC 512
#define EE 64
#define FF 256
#define NCOARSE (BB*HC*WC)   // 16384
#define NFINE   (BB*HF*WF)   // 65536

// ---------------- scratch ----------------
__device__ float g_coarse_n[(size_t)NCOARSE*CC];
__device__ float g_gate[NCOARSE];
__device__ float g_k[(size_t)NCOARSE*EE];
__device__ float g_qc[(size_t)NCOARSE*EE];
__device__ float g_v[(size_t)NCOARSE*FF];
__device__ float g_query[(size_t)NFINE*EE];
__device__ float g_mean[NFINE];
__device__ float g_rstd[NFINE];
__device__ float g_wfold[(size_t)CF*EE];
__device__ float g_dvec[EE];
__device__ float g_cvec[EE];

// ================= kernel 1: LN(coarse) + gate =================
__global__ void __launch_bounds__(128) ln_coarse_gate(
    const float* __restrict__ x, const float* __restrict__ g, const float* __restrict__ b,
    const float* __restrict__ wg, const float* __restrict__ bg)
{
    int row = blockIdx.x; int t = threadIdx.x;
    const float4* xr = (const float4*)(x + (size_t)row*CC);
    float4 v = xr[t];
    float s  = v.x+v.y+v.z+v.w;
    float sq = v.x*v.x+v.y*v.y+v.z*v.z+v.w*v.w;
    #pragma unroll
    for (int o=16;o;o>>=1){ s += __shfl_xor_sync(0xffffffffu,s,o); sq += __shfl_xor_sync(0xffffffffu,sq,o); }
    __shared__ float red[8];
    int wid = t>>5, l = t&31;
    if (l==0){ red[wid]=s; red[4+wid]=sq; }
    __syncthreads();
    s  = red[0]+red[1]+red[2]+red[3];
    sq = red[4]+red[5]+red[6]+red[7];
    float mean = s*(1.f/512.f);
    float var  = sq*(1.f/512.f) - mean*mean;
    float rstd = rsqrtf(var + 1e-3f);
    float4 gv = ((const float4*)g)[t];
    float4 bv = ((const float4*)b)[t];
    float4 o;
    o.x = (v.x-mean)*rstd*gv.x + bv.x;
    o.y = (v.y-mean)*rstd*gv.y + bv.y;
    o.z = (v.z-mean)*rstd*gv.z + bv.z;
    o.w = (v.w-mean)*rstd*gv.w + bv.w;
    ((float4*)(g_coarse_n + (size_t)row*CC))[t] = o;
    float4 wv = ((const float4*)wg)[t];
    float gd = o.x*wv.x + o.y*wv.y + o.z*wv.z + o.w*wv.w;
    #pragma unroll
    for (int oo=16;oo;oo>>=1) gd += __shfl_xor_sync(0xffffffffu,gd,oo);
    __syncthreads();
    if (l==0) red[wid]=gd;
    __syncthreads();
    if (t==0){
        float tot = red[0]+red[1]+red[2]+red[3] + bg[0];
        g_gate[row] = 1.f/(1.f+__expf(-tot));
    }
}

// ================= kernel 2: fine LN stats (warp per row of 256) =================
__global__ void __launch_bounds__(256) fine_stats(const float* __restrict__ x)
{
    int w = threadIdx.x>>5, l = threadIdx.x&31;
    int row = blockIdx.x*8 + w;
    const float4* xr = (const float4*)(x + (size_t)row*CF);
    float4 a = xr[l], c = xr[l+32];
    float s  = a.x+a.y+a.z+a.w + c.x+c.y+c.z+c.w;
    float sq = a.x*a.x+a.y*a.y+a.z*a.z+a.w*a.w + c.x*c.x+c.y*c.y+c.z*c.z+c.w*c.w;
    #pragma unroll
    for (int o=16;o;o>>=1){ s += __shfl_xor_sync(0xffffffffu,s,o); sq += __shfl_xor_sync(0xffffffffu,sq,o); }
    if (l==0){
        float m = s*(1.f/256.f);
        g_mean[row] = m;
        g_rstd[row] = rsqrtf(sq*(1.f/256.f) - m*m + 1e-3f);
    }
}

// ================= kernel 3: fold LN(fine) params into w_qf =================
__global__ void __launch_bounds__(64) fold_qf(
    const float* __restrict__ wqf, const float* __restrict__ bqf,
    const float* __restrict__ g, const float* __restrict__ bb)
{
    int n = threadIdx.x;
    float d=0.f, cv=0.f;
    for (int k=0;k<CF;k++){
        float wv = wqf[k*EE+n];
        float wf = g[k]*wv;
        g_wfold[k*EE+n] = wf;
        d += wf;
        cv += bb[k]*wv;
    }
    g_dvec[n]=d; g_cvec[n]=cv + bqf[n];
}

// ================= SGEMM: C[M,N] = A[M,K] @ W[K,N] + bias =================
// block tile 128x64, BK=16, 256 threads, thread tile 8m x 4n (f32x2 packed in n)
__global__ void __launch_bounds__(256) proj_gemm(
    const float* __restrict__ A, const float* __restrict__ W,
    const float* __restrict__ bias, float* __restrict__ C,
    int Kdim, int Ndim)
{
    __shared__ __align__(16) float As[16][128];
    __shared__ __align__(16) float Bs[16][64];
    int m0 = blockIdx.x*128, n0 = blockIdx.y*64;
    int t = threadIdx.x;
    int mA = t>>1, kq = (t&1)*8;
    int kB = t>>4, n4 = (t&15)*4;
    int ty = t>>4, tx = t&15;

    const float* Aload = A + (size_t)(m0+mA)*Kdim + kq;
    const float* Wload = W + (size_t)kB*Ndim + n0 + n4;

    ull acc[8][2];
    #pragma unroll
    for (int i=0;i<8;i++){ acc[i][0]=pk2(0.f,0.f); acc[i][1]=pk2(0.f,0.f); }

    int KB = Kdim/16;
    float4 ra0 = *(const float4*)(Aload);
    float4 ra1 = *(const float4*)(Aload+4);
    float4 rb  = *(const float4*)(Wload);
    for (int kb=0; kb<KB; kb++){
        As[kq+0][mA]=ra0.x; As[kq+1][mA]=ra0.y; As[kq+2][mA]=ra0.z; As[kq+3][mA]=ra0.w;
        As[kq+4][mA]=ra1.x; As[kq+5][mA]=ra1.y; As[kq+6][mA]=ra1.z; As[kq+7][mA]=ra1.w;
        *(float4*)&Bs[kB][n4] = rb;
        __syncthreads();
        if (kb+1<KB){
            ra0 = *(const float4*)(Aload + (kb+1)*16);
            ra1 = *(const float4*)(Aload + (kb+1)*16 + 4);
            rb  = *(const float4*)(Wload + (size_t)(kb+1)*16*Ndim);
        }
        #pragma unroll
        for (int k=0;k<16;k++){
            ull b01 = *(const ull*)&Bs[k][tx*4];
            ull b23 = *(const ull*)&Bs[k][tx*4+2];
            #pragma unroll
            for (int i=0;i<8;i++){
                float av = As[k][ty*8+i];
                ull aP = pk2(av,av);
                ffma2(acc[i][0], aP, b01);
                ffma2(acc[i][1], aP, b23);
            }
        }
        __syncthreads();
    }
    float4 bb = *(const float4*)(bias + n0 + tx*4);
    #pragma unroll
    for (int i=0;i<8;i++){
        int m = m0 + ty*8 + i;
        float2 u0 = upk(acc[i][0]), u1 = upk(acc[i][1]);
        float4 o = make_float4(u0.x+bb.x, u0.y+bb.y, u1.x+bb.z, u1.y+bb.w);
        *(float4*)&C[(size_t)m*Ndim + n0 + tx*4] = o;
    }
}

// ================= query GEMM with folded LN + gate blend =================
__global__ void __launch_bounds__(256) query_gemm(const float* __restrict__ fine)
{
    __shared__ __align__(16) float As[16][128];
    __shared__ __align__(16) float Bs[16][64];
    int m0 = blockIdx.x*128;
    int t = threadIdx.x;
    int mA = t>>1, kq = (t&1)*8;
    int kB = t>>4, n4 = (t&15)*4;
    int ty = t>>4, tx = t&15;

    const float* Aload = fine + (size_t)(m0+mA)*CF + kq;
    const float* Wload = g_wfold + (size_t)kB*EE + n4;

    ull acc[8][2];
    #pragma unroll
    for (int i=0;i<8;i++){ acc[i][0]=pk2(0.f,0.f); acc[i][1]=pk2(0.f,0.f); }

    const int KB = CF/16;  // 16
    float4 ra0 = *(const float4*)(Aload);
    float4 ra1 = *(const float4*)(Aload+4);
    float4 rb  = *(const float4*)(Wload);
    for (int kb=0; kb<KB; kb++){
        As[kq+0][mA]=ra0.x; As[kq+1][mA]=ra0.y; As[kq+2][mA]=ra0.z; As[kq+3][mA]=ra0.w;
        As[kq+4][mA]=ra1.x; As[kq+5][mA]=ra1.y; As[kq+6][mA]=ra1.z; As[kq+7][mA]=ra1.w;
        *(float4*)&Bs[kB][n4] = rb;
        __syncthreads();
        if (kb+1<KB){
            ra0 = *(const float4*)(Aload + (kb+1)*16);
            ra1 = *(const float4*)(Aload + (kb+1)*16 + 4);
            rb  = *(const float4*)(Wload + (size_t)(kb+1)*16*EE);
        }
        #pragma unroll
        for (int k=0;k<16;k++){
            ull b01 = *(const ull*)&Bs[k][tx*4];
            ull b23 = *(const ull*)&Bs[k][tx*4+2];
            #pragma unroll
            for (int i=0;i<8;i++){
                float av = As[k][ty*8+i];
                ull aP = pk2(av,av);
                ffma2(acc[i][0], aP, b01);
                ffma2(acc[i][1], aP, b23);
            }
        }
        __syncthreads();
    }
    float4 dv = *(const float4*)&g_dvec[tx*4];
    float4 cv = *(const float4*)&g_cvec[tx*4];
    #pragma unroll
    for (int i=0;i<8;i++){
        int m = m0 + ty*8 + i;
        float mean = g_mean[m], rstd = g_rstd[m];
        int b_ = m>>14, h = (m>>7)&127, w = m&127;
        int mc = (b_<<12) | ((h>>1)<<6) | (w>>1);
        float gt = g_gate[mc];
        float4 qc4 = *(const float4*)&g_qc[(size_t)mc*EE + tx*4];
        float2 u0 = upk(acc[i][0]), u1 = upk(acc[i][1]);
        float4 q;
        q.x = rstd*(u0.x - mean*dv.x) + cv.x;
        q.y = rstd*(u0.y - mean*dv.y) + cv.y;
        q.z = rstd*(u1.x - mean*dv.z) + cv.z;
        q.w = rstd*(u1.y - mean*dv.w) + cv.w;
        float4 o;
        o.x = q.x*gt + qc4.x*(1.f-gt);
        o.y = q.y*gt + qc4.y*(1.f-gt);
        o.z = q.z*gt + qc4.z*(1.f-gt);
        o.w = q.w*gt + qc4.w*(1.f-gt);
        *(float4*)&g_query[(size_t)m*EE + tx*4] = o;
    }
}

// ================= local attention =================
#define SK_STRIDE 68
#define ATT_SMEM_BYTES ((6800 + 25600 + 4096 + 64*28) * 4)
__global__ void __launch_bounds__(256) attn_kernel(float* __restrict__ out)
{
    extern __shared__ __align__(16) float sm[];
    float* sk = sm;                       // [5][20][68]
    float* sv = sm + 6800;                // [5][20][256]
    float* sq = sm + 6800 + 25600;        // [64][64]
    float* satt = sq + 4096;              // [64][28]

    int j0 = blockIdx.x * 16;
    int i  = blockIdx.y;
    int b  = blockIdx.z;
    int t = threadIdx.x;

    // stage keys (zero-padded borders)
    for (int idx = t; idx < 1600; idx += 256){
        int c4 = idx & 15, cc = (idx>>4) % 20, r = idx/320;
        int ci = i - 2 + r, cj = j0 - 2 + cc;
        float4 v = make_float4(0.f,0.f,0.f,0.f);
        if (ci>=0 && ci<HC && cj>=0 && cj<WC)
            v = *(const float4*)&g_k[(((size_t)(b*HC+ci)*WC + cj)<<6) + c4*4];
        *(float4*)&sk[(r*20+cc)*SK_STRIDE + c4*4] = v;
    }
    // stage values
    for (int idx = t; idx < 6400; idx += 256){
        int c4 = idx & 63, cc = (idx>>6) % 20, r = idx/1280;
        int ci = i - 2 + r, cj = j0 - 2 + cc;
        float4 v = make_float4(0.f,0.f,0.f,0.f);
        if (ci>=0 && ci<HC && cj>=0 && cj<WC)
            v = *(const float4*)&g_v[(((size_t)(b*HC+ci)*WC + cj)<<8) + c4*4];
        *(float4*)&sv[(r*20+cc)*256 + c4*4] = v;
    }
    // stage queries: fp = cp*4 + di*2 + dj
    for (int idx = t; idx < 1024; idx += 256){
        int c4 = idx & 15, fp = idx >> 4;
        int cp = fp>>2, q = fp&3, di = q>>1, dj = q&1;
        int h = 2*i + di, w = 2*(j0+cp) + dj;
        *(float4*)&sq[fp*64 + c4*4] =
            *(const float4*)&g_query[(((size_t)(b*HF+h)*WF + w)<<6) + c4*4];
    }
    __syncthreads();

    // scores + softmax: warp per 8 fine pixels, lane per patch
    int wd = t>>5, l = t&31;
    int pr = l/5, pc = l - pr*5;
    for (int fi=0; fi<8; fi++){
        int fp = wd*8 + fi;
        int cp = fp>>2;
        float s = -1e30f;
        if (l < 25){
            s = 0.f;
            const float* kk = &sk[(pr*20 + cp + pc)*SK_STRIDE];
            const float* qq = &sq[fp*64];
            #pragma unroll
            for (int c4=0;c4<16;c4++){
                float4 qa = *(const float4*)(qq + c4*4);
                float4 ka = *(const float4*)(kk + c4*4);
                s += qa.x*ka.x + qa.y*ka.y + qa.z*ka.z + qa.w*ka.w;
            }
        }
        float mx = s;
        #pragma unroll
        for (int o=16;o;o>>=1) mx = fmaxf(mx, __shfl_xor_sync(0xffffffffu,mx,o));
        float e = (l<25) ? __expf(s - mx) : 0.f;
        float ssum = e;
        #pragma unroll
        for (int o=16;o;o>>=1) ssum += __shfl_xor_sync(0xffffffffu,ssum,o);
        if (l<25) satt[fp*28 + l] = e / ssum;
    }
    __syncthreads();

    // value pass: 16 threads per coarse pixel, each covers 4 channels x 4 fine pixels
    int cp = t>>4, l16 = t&15;
    for (int cg=0; cg<4; cg++){
        int c = cg*64 + l16*4;
        ull acc[4][2];
        #pragma unroll
        for (int q=0;q<4;q++){ acc[q][0]=pk2(0.f,0.f); acc[q][1]=pk2(0.f,0.f); }
        #pragma unroll
        for (int p=0;p<25;p++){
            int ppr = p/5, ppc = p - ppr*5;
            const ull* vp = (const ull*)&sv[(ppr*20 + cp + ppc)*256 + c];
            ull v01 = vp[0], v23 = vp[1];
            #pragma unroll
            for (int q=0;q<4;q++){
                float a = satt[(cp*4+q)*28 + p];
                ull aP = pk2(a,a);
                ffma2(acc[q][0], aP, v01);
                ffma2(acc[q][1], aP, v23);
            }
        }
        #pragma unroll
        for (int q=0;q<4;q++){
            int di=q>>1, dj=q&1;
            int h = 2*i+di, w = 2*(j0+cp)+dj;
            float2 u0=upk(acc[q][0]), u1=upk(acc[q][1]);
            float4 o = make_float4(u0.x,u0.y,u1.x,u1.y);
            *(float4*)&out[(((size_t)(b*HF+h)*WF + w)<<8) + c] = o;
        }
    }
}

// ================= launch =================
extern "C" void kernel_launch(void* const* d_in, const int* in_sizes, int n_in,
                              void* d_out, int out_size)
{
    (void)in_sizes; (void)n_in; (void)out_size;
    const float* fine   = (const float*)d_in[0];
    const float* coarse = (const float*)d_in[1];
    const float* ln_f_g = (const float*)d_in[2];
    const float* ln_f_b = (const float*)d_in[3];
    const float* ln_c_g = (const float*)d_in[4];
    const float* ln_c_b = (const float*)d_in[5];
    const float* w_gate = (const float*)d_in[6];
    const float* b_gate = (const float*)d_in[7];
    const float* w_qf   = (const float*)d_in[8];
    const float* b_qf   = (const float*)d_in[9];
    const float* w_qc   = (const float*)d_in[10];
    const float* b_qc   = (const float*)d_in[11];
    const float* w_k    = (const float*)d_in[12];
    const float* b_k    = (const float*)d_in[13];
    const float* w_v    = (const float*)d_in[14];
    const float* b_v    = (const float*)d_in[15];
    float* out = (float*)d_out;

    void *p_cn, *p_k, *p_qc, *p_v;
    cudaGetSymbolAddress(&p_cn, g_coarse_n);
    cudaGetSymbolAddress(&p_k,  g_k);
    cudaGetSymbolAddress(&p_qc, g_qc);
    cudaGetSymbolAddress(&p_v,  g_v);

    ln_coarse_gate<<<NCOARSE, 128>>>(coarse, ln_c_g, ln_c_b, w_gate, b_gate);
    fine_stats<<<NFINE/8, 256>>>(fine);
    fold_qf<<<1, 64>>>(w_qf, b_qf, ln_f_g, ln_f_b);

    proj_gemm<<<dim3(NCOARSE/128,1), 256>>>((const float*)p_cn, w_k,  b_k,  (float*)p_k,  CC, EE);
    proj_gemm<<<dim3(NCOARSE/128,1), 256>>>((const float*)p_cn, w_qc, b_qc, (float*)p_qc, CC, EE);
    proj_gemm<<<dim3(NCOARSE/128,4), 256>>>((const float*)p_cn, w_v,  b_v,  (float*)p_v,  CC, FF);

    query_gemm<<<dim3(NFINE/128,1), 256>>>(fine);

    cudaFuncSetAttribute(attn_kernel, cudaFuncAttributeMaxDynamicSharedMemorySize, ATT_SMEM_BYTES);
    attn_kernel<<<dim3(WC/16, HC, BB), 256, ATT_SMEM_BYTES>>>(out);
}

// round 3
// speedup vs baseline: 1.1442x; 1.1442x over previous
#include <cuda_runtime.h>
#include <cuda_bf16.h>
#include <cstdint>
#include <cstddef>

typedef unsigned long long ull;

__device__ __forceinline__ void ffma2(ull& d, ull a, ull b){
    asm("fma.rn.f32x2 %0, %1, %2, %0;" : "+l"(d) : "l"(a), "l"(b));
}
__device__ __forceinline__ ull pk2(float x, float y){
    ull r; asm("mov.b64 %0, {%1, %2};" : "=l"(r) : "f"(x), "f"(y)); return r;
}
__device__ __forceinline__ float2 upk(ull a){
    float2 r; asm("mov.b64 {%0, %1}, %2;" : "=f"(r.x), "=f"(r.y) : "l"(a)); return r;
}

// ---------------- fixed shapes ----------------
#define BB 4
#define HF 128
#define WF 128
#define CF 256
#define HC 64
#define WC 64
#define CC 512
#define EE 64
#define FF 256
#define NP 384           // fused projection width: [k(64) | qc(64) | v(256)]
#define NCOARSE (BB*HC*WC)   // 16384
#define NFINE   (BB*HF*WF)   // 65536

// ---------------- scratch ----------------
__device__ float g_coarse_n[(size_t)NCOARSE*CC];
__device__ float g_gate[NCOARSE];
__device__ float g_proj[(size_t)NCOARSE*NP];   // fused k|qc|v
__device__ float g_query[(size_t)NFINE*EE];
__device__ float g_mean[NFINE];
__device__ float g_rstd[NFINE];
__device__ float g_wfold[(size_t)CF*EE];
__device__ float g_dvec[EE];
__device__ float g_cvec[EE];
__device__ float g_wcat[(size_t)CC*NP];
__device__ float g_bcat[NP];

// ================= kernel 1: LN(coarse) + gate =================
__global__ void __launch_bounds__(128) ln_coarse_gate(
    const float* __restrict__ x, const float* __restrict__ g, const float* __restrict__ b,
    const float* __restrict__ wg, const float* __restrict__ bg)
{
    int row = blockIdx.x; int t = threadIdx.x;
    const float4* xr = (const float4*)(x + (size_t)row*CC);
    float4 v = xr[t];
    float s  = v.x+v.y+v.z+v.w;
    float sq = v.x*v.x+v.y*v.y+v.z*v.z+v.w*v.w;
    #pragma unroll
    for (int o=16;o;o>>=1){ s += __shfl_xor_sync(0xffffffffu,s,o); sq += __shfl_xor_sync(0xffffffffu,sq,o); }
    __shared__ float red[8];
    int wid = t>>5, l = t&31;
    if (l==0){ red[wid]=s; red[4+wid]=sq; }
    __syncthreads();
    s  = red[0]+red[1]+red[2]+red[3];
    sq = red[4]+red[5]+red[6]+red[7];
    float mean = s*(1.f/512.f);
    float var  = sq*(1.f/512.f) - mean*mean;
    float rstd = rsqrtf(var + 1e-3f);
    float4 gv = ((const float4*)g)[t];
    float4 bv = ((const float4*)b)[t];
    float4 o;
    o.x = (v.x-mean)*rstd*gv.x + bv.x;
    o.y = (v.y-mean)*rstd*gv.y + bv.y;
    o.z = (v.z-mean)*rstd*gv.z + bv.z;
    o.w = (v.w-mean)*rstd*gv.w + bv.w;
    ((float4*)(g_coarse_n + (size_t)row*CC))[t] = o;
    float4 wv = ((const float4*)wg)[t];
    float gd = o.x*wv.x + o.y*wv.y + o.z*wv.z + o.w*wv.w;
    #pragma unroll
    for (int oo=16;oo;oo>>=1) gd += __shfl_xor_sync(0xffffffffu,gd,oo);
    __syncthreads();
    if (l==0) red[wid]=gd;
    __syncthreads();
    if (t==0){
        float tot = red[0]+red[1]+red[2]+red[3] + bg[0];
        g_gate[row] = 1.f/(1.f+__expf(-tot));
    }
}

// ================= kernel 2: fine LN stats (warp per row of 256) =================
__global__ void __launch_bounds__(256) fine_stats(const float* __restrict__ x)
{
    int w = threadIdx.x>>5, l = threadIdx.x&31;
    int row = blockIdx.x*8 + w;
    const float4* xr = (const float4*)(x + (size_t)row*CF);
    float4 a = xr[l], c = xr[l+32];
    float s  = a.x+a.y+a.z+a.w + c.x+c.y+c.z+c.w;
    float sq = a.x*a.x+a.y*a.y+a.z*a.z+a.w*a.w + c.x*c.x+c.y*c.y+c.z*c.z+c.w*c.w;
    #pragma unroll
    for (int o=16;o;o>>=1){ s += __shfl_xor_sync(0xffffffffu,s,o); sq += __shfl_xor_sync(0xffffffffu,sq,o); }
    if (l==0){
        float m = s*(1.f/256.f);
        g_mean[row] = m;
        g_rstd[row] = rsqrtf(sq*(1.f/256.f) - m*m + 1e-3f);
    }
}

// ================= pack weights: wcat = [w_k | w_qc | w_v], bcat =================
__global__ void __launch_bounds__(384) pack_w(
    const float* __restrict__ wk, const float* __restrict__ wqc, const float* __restrict__ wv,
    const float* __restrict__ bk, const float* __restrict__ bqc, const float* __restrict__ bv)
{
    int k = blockIdx.x; int n = threadIdx.x;
    float v;
    if (n < 64)       v = wk [k*64  + n];
    else if (n < 128) v = wqc[k*64  + (n-64)];
    else              v = wv [k*256 + (n-128)];
    g_wcat[(size_t)k*NP + n] = v;
    if (k == 0){
        float bvv = (n<64) ? bk[n] : (n<128) ? bqc[n-64] : bv[n-128];
        g_bcat[n] = bvv;
    }
}

// ================= fold LN(fine) params into w_qf =================
__global__ void __launch_bounds__(256) fold_qf(
    const float* __restrict__ wqf, const float* __restrict__ bqf,
    const float* __restrict__ g, const float* __restrict__ bb)
{
    __shared__ float sd[256], sc[256];
    int t = threadIdx.x; int n = t&63, seg = t>>6;
    float d=0.f, cv=0.f;
    for (int k=seg*64; k<seg*64+64; k++){
        float wv = wqf[k*EE+n];
        float wf = g[k]*wv;
        g_wfold[k*EE+n] = wf;
        d += wf;
        cv += bb[k]*wv;
    }
    sd[t]=d; sc[t]=cv;
    __syncthreads();
    if (t < 64){
        float dd = sd[t]+sd[t+64]+sd[t+128]+sd[t+192];
        float cc = sc[t]+sc[t+64]+sc[t+128]+sc[t+192];
        g_dvec[t]=dd; g_cvec[t]=cc + bqf[t];
    }
}

// ================= fused projection GEMM: proj[16384,384] = coarse_n @ wcat + bcat =================
// block tile 128x64, BK=16, 256 threads; thread tile 8m x 4n; A read as LDS.64 m-pairs
__global__ void __launch_bounds__(256) proj_gemm()
{
    __shared__ __align__(16) float As[16][128];
    __shared__ __align__(16) float Bs[16][64];
    int m0 = blockIdx.x*128, n0 = blockIdx.y*64;
    int t = threadIdx.x;
    int mA = t>>1, kq = (t&1)*8;
    int kB = t>>4, n4 = (t&15)*4;
    int ty = t>>4, tx = t&15;

    const float* Aload = g_coarse_n + (size_t)(m0+mA)*CC + kq;
    const float* Wload = g_wcat + (size_t)kB*NP + n0 + n4;

    ull acc[4][4];   // [n][m-pair]
    #pragma unroll
    for (int n=0;n<4;n++)
        #pragma unroll
        for (int mp=0;mp<4;mp++) acc[n][mp]=pk2(0.f,0.f);

    const int KB = CC/16;
    float4 ra0 = *(const float4*)(Aload);
    float4 ra1 = *(const float4*)(Aload+4);
    float4 rb  = *(const float4*)(Wload);
    for (int kb=0; kb<KB; kb++){
        As[kq+0][mA]=ra0.x; As[kq+1][mA]=ra0.y; As[kq+2][mA]=ra0.z; As[kq+3][mA]=ra0.w;
        As[kq+4][mA]=ra1.x; As[kq+5][mA]=ra1.y; As[kq+6][mA]=ra1.z; As[kq+7][mA]=ra1.w;
        *(float4*)&Bs[kB][n4] = rb;
        __syncthreads();
        if (kb+1<KB){
            ra0 = *(const float4*)(Aload + (kb+1)*16);
            ra1 = *(const float4*)(Aload + (kb+1)*16 + 4);
            rb  = *(const float4*)(Wload + (size_t)(kb+1)*16*NP);
        }
        #pragma unroll
        for (int k=0;k<16;k++){
            ull a0 = *(const ull*)&As[k][ty*8+0];
            ull a1 = *(const ull*)&As[k][ty*8+2];
            ull a2 = *(const ull*)&As[k][ty*8+4];
            ull a3 = *(const ull*)&As[k][ty*8+6];
            float b0 = Bs[k][tx*4+0], b1 = Bs[k][tx*4+1];
            float b2 = Bs[k][tx*4+2], b3 = Bs[k][tx*4+3];
            ull B0=pk2(b0,b0), B1=pk2(b1,b1), B2=pk2(b2,b2), B3=pk2(b3,b3);
            ffma2(acc[0][0],a0,B0); ffma2(acc[0][1],a1,B0); ffma2(acc[0][2],a2,B0); ffma2(acc[0][3],a3,B0);
            ffma2(acc[1][0],a0,B1); ffma2(acc[1][1],a1,B1); ffma2(acc[1][2],a2,B1); ffma2(acc[1][3],a3,B1);
            ffma2(acc[2][0],a0,B2); ffma2(acc[2][1],a1,B2); ffma2(acc[2][2],a2,B2); ffma2(acc[2][3],a3,B2);
            ffma2(acc[3][0],a0,B3); ffma2(acc[3][1],a1,B3); ffma2(acc[3][2],a2,B3); ffma2(acc[3][3],a3,B3);
        }
        __syncthreads();
    }
    float4 bb = *(const float4*)&g_bcat[n0 + tx*4];
    #pragma unroll
    for (int mp=0; mp<4; mp++){
        float2 c0=upk(acc[0][mp]), c1=upk(acc[1][mp]), c2=upk(acc[2][mp]), c3=upk(acc[3][mp]);
        int r0 = m0 + ty*8 + 2*mp;
        *(float4*)&g_proj[(size_t)r0*NP + n0 + tx*4] =
            make_float4(c0.x+bb.x, c1.x+bb.y, c2.x+bb.z, c3.x+bb.w);
        *(float4*)&g_proj[(size_t)(r0+1)*NP + n0 + tx*4] =
            make_float4(c0.y+bb.x, c1.y+bb.y, c2.y+bb.z, c3.y+bb.w);
    }
}

// ================= query GEMM with folded LN + gate blend =================
__global__ void __launch_bounds__(256) query_gemm(const float* __restrict__ fine)
{
    __shared__ __align__(16) float As[16][128];
    __shared__ __align__(16) float Bs[16][64];
    int m0 = blockIdx.x*128;
    int t = threadIdx.x;
    int mA = t>>1, kq = (t&1)*8;
    int kB = t>>4, n4 = (t&15)*4;
    int ty = t>>4, tx = t&15;

    const float* Aload = fine + (size_t)(m0+mA)*CF + kq;
    const float* Wload = g_wfold + (size_t)kB*EE + n4;

    ull acc[4][4];
    #pragma unroll
    for (int n=0;n<4;n++)
        #pragma unroll
        for (int mp=0;mp<4;mp++) acc[n][mp]=pk2(0.f,0.f);

    const int KB = CF/16;
    float4 ra0 = *(const float4*)(Aload);
    float4 ra1 = *(const float4*)(Aload+4);
    float4 rb  = *(const float4*)(Wload);
    for (int kb=0; kb<KB; kb++){
        As[kq+0][mA]=ra0.x; As[kq+1][mA]=ra0.y; As[kq+2][mA]=ra0.z; As[kq+3][mA]=ra0.w;
        As[kq+4][mA]=ra1.x; As[kq+5][mA]=ra1.y; As[kq+6][mA]=ra1.z; As[kq+7][mA]=ra1.w;
        *(float4*)&Bs[kB][n4] = rb;
        __syncthreads();
        if (kb+1<KB){
            ra0 = *(const float4*)(Aload + (kb+1)*16);
            ra1 = *(const float4*)(Aload + (kb+1)*16 + 4);
            rb  = *(const float4*)(Wload + (size_t)(kb+1)*16*EE);
        }
        #pragma unroll
        for (int k=0;k<16;k++){
            ull a0 = *(const ull*)&As[k][ty*8+0];
            ull a1 = *(const ull*)&As[k][ty*8+2];
            ull a2 = *(const ull*)&As[k][ty*8+4];
            ull a3 = *(const ull*)&As[k][ty*8+6];
            float b0 = Bs[k][tx*4+0], b1 = Bs[k][tx*4+1];
            float b2 = Bs[k][tx*4+2], b3 = Bs[k][tx*4+3];
            ull B0=pk2(b0,b0), B1=pk2(b1,b1), B2=pk2(b2,b2), B3=pk2(b3,b3);
            ffma2(acc[0][0],a0,B0); ffma2(acc[0][1],a1,B0); ffma2(acc[0][2],a2,B0); ffma2(acc[0][3],a3,B0);
            ffma2(acc[1][0],a0,B1); ffma2(acc[1][1],a1,B1); ffma2(acc[1][2],a2,B1); ffma2(acc[1][3],a3,B1);
            ffma2(acc[2][0],a0,B2); ffma2(acc[2][1],a1,B2); ffma2(acc[2][2],a2,B2); ffma2(acc[2][3],a3,B2);
            ffma2(acc[3][0],a0,B3); ffma2(acc[3][1],a1,B3); ffma2(acc[3][2],a2,B3); ffma2(acc[3][3],a3,B3);
        }
        __syncthreads();
    }
    float4 dv = *(const float4*)&g_dvec[tx*4];
    float4 cv = *(const float4*)&g_cvec[tx*4];
    #pragma unroll
    for (int mp=0; mp<4; mp++){
        float2 c0=upk(acc[0][mp]), c1=upk(acc[1][mp]), c2=upk(acc[2][mp]), c3=upk(acc[3][mp]);
        #pragma unroll
        for (int rr=0; rr<2; rr++){
            int m = m0 + ty*8 + 2*mp + rr;
            float4 u = rr ? make_float4(c0.y,c1.y,c2.y,c3.y)
                          : make_float4(c0.x,c1.x,c2.x,c3.x);
            float mean = g_mean[m], rstd = g_rstd[m];
            int b_ = m>>14, h = (m>>7)&127, w = m&127;
            int mc = (b_<<12) | ((h>>1)<<6) | (w>>1);
            float gt = g_gate[mc];
            float4 qc4 = *(const float4*)&g_proj[(size_t)mc*NP + 64 + tx*4];
            float4 q;
            q.x = rstd*(u.x - mean*dv.x) + cv.x;
            q.y = rstd*(u.y - mean*dv.y) + cv.y;
            q.z = rstd*(u.z - mean*dv.z) + cv.z;
            q.w = rstd*(u.w - mean*dv.w) + cv.w;
            float4 o;
            o.x = q.x*gt + qc4.x*(1.f-gt);
            o.y = q.y*gt + qc4.y*(1.f-gt);
            o.z = q.z*gt + qc4.z*(1.f-gt);
            o.w = q.w*gt + qc4.w*(1.f-gt);
            *(float4*)&g_query[(size_t)m*EE + tx*4] = o;
        }
    }
}

// ================= local attention =================
#define SK_STRIDE 68
#define ATT_SMEM_BYTES ((6800 + 25600 + 4096 + 64*28) * 4)
__global__ void __launch_bounds__(256) attn_kernel(float* __restrict__ out)
{
    extern __shared__ __align__(16) float sm[];
    float* sk = sm;                       // [5][20][68]
    float* sv = sm + 6800;                // [5][20][256]
    float* sq = sm + 6800 + 25600;        // [64][64]
    float* satt = sq + 4096;              // [64][28]

    int j0 = blockIdx.x * 16;
    int i  = blockIdx.y;
    int b  = blockIdx.z;
    int t = threadIdx.x;

    // stage keys (zero-padded borders): proj cols [0,64)
    for (int idx = t; idx < 1600; idx += 256){
        int c4 = idx & 15, cc = (idx>>4) % 20, r = idx/320;
        int ci = i - 2 + r, cj = j0 - 2 + cc;
        float4 v = make_float4(0.f,0.f,0.f,0.f);
        if (ci>=0 && ci<HC && cj>=0 && cj<WC)
            v = *(const float4*)&g_proj[(size_t)((b*HC+ci)*WC + cj)*NP + c4*4];
        *(float4*)&sk[(r*20+cc)*SK_STRIDE + c4*4] = v;
    }
    // stage values: proj cols [128,384)
    for (int idx = t; idx < 6400; idx += 256){
        int c4 = idx & 63, cc = (idx>>6) % 20, r = idx/1280;
        int ci = i - 2 + r, cj = j0 - 2 + cc;
        float4 v = make_float4(0.f,0.f,0.f,0.f);
        if (ci>=0 && ci<HC && cj>=0 && cj<WC)
            v = *(const float4*)&g_proj[(size_t)((b*HC+ci)*WC + cj)*NP + 128 + c4*4];
        *(float4*)&sv[(r*20+cc)*256 + c4*4] = v;
    }
    // stage queries: fp = cp*4 + di*2 + dj
    for (int idx = t; idx < 1024; idx += 256){
        int c4 = idx & 15, fp = idx >> 4;
        int cp = fp>>2, q = fp&3, di = q>>1, dj = q&1;
        int h = 2*i + di, w = 2*(j0+cp) + dj;
        *(float4*)&sq[fp*64 + c4*4] =
            *(const float4*)&g_query[(((size_t)(b*HF+h)*WF + w)<<6) + c4*4];
    }
    __syncthreads();

    // scores + softmax: warp per 8 fine pixels, lane per patch
    int wd = t>>5, l = t&31;
    int pr = l/5, pc = l - pr*5;
    for (int fi=0; fi<8; fi++){
        int fp = wd*8 + fi;
        int cp = fp>>2;
        float s = -1e30f;
        if (l < 25){
            s = 0.f;
            const float* kk = &sk[(pr*20 + cp + pc)*SK_STRIDE];
            const float* qq = &sq[fp*64];
            #pragma unroll
            for (int c4=0;c4<16;c4++){
                float4 qa = *(const float4*)(qq + c4*4);
                float4 ka = *(const float4*)(kk + c4*4);
                s += qa.x*ka.x + qa.y*ka.y + qa.z*ka.z + qa.w*ka.w;
            }
        }
        float mx = s;
        #pragma unroll
        for (int o=16;o;o>>=1) mx = fmaxf(mx, __shfl_xor_sync(0xffffffffu,mx,o));
        float e = (l<25) ? __expf(s - mx) : 0.f;
        float ssum = e;
        #pragma unroll
        for (int o=16;o;o>>=1) ssum += __shfl_xor_sync(0xffffffffu,ssum,o);
        if (l<25) satt[fp*28 + l] = e / ssum;
    }
    __syncthreads();

    // value pass: 16 threads per coarse pixel
    int cp = t>>4, l16 = t&15;
    for (int cg=0; cg<4; cg++){
        int c = cg*64 + l16*4;
        ull acc[4][2];
        #pragma unroll
        for (int q=0;q<4;q++){ acc[q][0]=pk2(0.f,0.f); acc[q][1]=pk2(0.f,0.f); }
        #pragma unroll
        for (int p=0;p<25;p++){
            int ppr = p/5, ppc = p - ppr*5;
            const ull* vp = (const ull*)&sv[(ppr*20 + cp + ppc)*256 + c];
            ull v01 = vp[0], v23 = vp[1];
            #pragma unroll
            for (int q=0;q<4;q++){
                float a = satt[(cp*4+q)*28 + p];
                ull aP = pk2(a,a);
                ffma2(acc[q][0], aP, v01);
                ffma2(acc[q][1], aP, v23);
            }
        }
        #pragma unroll
        for (int q=0;q<4;q++){
            int di=q>>1, dj=q&1;
            int h = 2*i+di, w = 2*(j0+cp)+dj;
            float2 u0=upk(acc[q][0]), u1=upk(acc[q][1]);
            float4 o = make_float4(u0.x,u0.y,u1.x,u1.y);
            *(float4*)&out[(((size_t)(b*HF+h)*WF + w)<<8) + c] = o;
        }
    }
}

// ================= launch =================
extern "C" void kernel_launch(void* const* d_in, const int* in_sizes, int n_in,
                              void* d_out, int out_size)
{
    (void)in_sizes; (void)n_in; (void)out_size;
    const float* fine   = (const float*)d_in[0];
    const float* coarse = (const float*)d_in[1];
    const float* ln_f_g = (const float*)d_in[2];
    const float* ln_f_b = (const float*)d_in[3];
    const float* ln_c_g = (const float*)d_in[4];
    const float* ln_c_b = (const float*)d_in[5];
    const float* w_gate = (const float*)d_in[6];
    const float* b_gate = (const float*)d_in[7];
    const float* w_qf   = (const float*)d_in[8];
    const float* b_qf   = (const float*)d_in[9];
    const float* w_qc   = (const float*)d_in[10];
    const float* b_qc   = (const float*)d_in[11];
    const float* w_k    = (const float*)d_in[12];
    const float* b_k    = (const float*)d_in[13];
    const float* w_v    = (const float*)d_in[14];
    const float* b_v    = (const float*)d_in[15];
    float* out = (float*)d_out;

    ln_coarse_gate<<<NCOARSE, 128>>>(coarse, ln_c_g, ln_c_b, w_gate, b_gate);
    pack_w<<<CC, NP>>>(w_k, w_qc, w_v, b_k, b_qc, b_v);
    fine_stats<<<NFINE/8, 256>>>(fine);
    fold_qf<<<1, 256>>>(w_qf, b_qf, ln_f_g, ln_f_b);

    proj_gemm<<<dim3(NCOARSE/128, NP/64), 256>>>();
    query_gemm<<<NFINE/128, 256>>>(fine);

    cudaFuncSetAttribute(attn_kernel, cudaFuncAttributeMaxDynamicSharedMemorySize, ATT_SMEM_BYTES);
    attn_kernel<<<dim3(WC/16, HC, BB), 256, ATT_SMEM_BYTES>>>(out);
}